// round 7
// baseline (speedup 1.0000x reference)
#include <cuda_runtime.h>
#include <cstdint>

// S4D Vandermonde kernel:  K[h,l] = 2 * sum_n C_eff[h,n] * exp(dtA[h,n] * l)
// H=256, NH=N/2=32, L=16384.
//
// With this problem's init dtA[h,n] is constant across n, so
// K[h,l] = S[h] * exp(dtA[h]*l): one geometric recurrence per head.
// R7: stores routed SMEM -> cp.async.bulk (STG.128 LSU issue = 42.7 B/cyc/SM
// was a ~2650 cyc/SM serial term; STS.128 runs at 128 B/cyc/SM and the bulk
// copy drains async at the L2 cap). Prologue: raw ex2.approx MUFUs (no
// log2e FMULs, exp(dtA) reused as q1) and __fdividef instead of IEEE div.
// Uniformity of dtA across n is still verified at runtime (warp ballot) with
// guarded-STG fallbacks for partial tiles and non-uniform heads.

#define TPB  256
#define NH   32
#define TILE 4096              // l-elements per block (16 KB tile)
#define JF   4                 // float4 values per thread
#define LOG2E 1.4426950408889634f

typedef unsigned long long ull;

__device__ __forceinline__ float ex2(float x) {
    float y; asm("ex2.approx.f32 %0, %1;" : "=f"(y) : "f"(x));
    return y;
}
__device__ __forceinline__ ull mul2(ull a, ull b) {
    ull d; asm("mul.rn.f32x2 %0, %1, %2;" : "=l"(d) : "l"(a), "l"(b));
    return d;
}
__device__ __forceinline__ ull pack2(float lo, float hi) {
    ull u; asm("mov.b64 %0, {%1, %2};" : "=l"(u) : "f"(lo), "f"(hi));
    return u;
}
__device__ __forceinline__ void unpack2(ull u, float& lo, float& hi) {
    asm("mov.b64 {%0, %1}, %2;" : "=f"(lo), "=f"(hi) : "l"(u));
}
__device__ __forceinline__ uint32_t smem_u32(const void* p) {
    uint32_t a;
    asm("{ .reg .u64 t; cvta.to.shared.u64 t, %1; cvt.u32.u64 %0, t; }"
        : "=r"(a) : "l"(p));
    return a;
}

__global__ void __launch_bounds__(TPB) s4d_kernel(
    const float* __restrict__ log_dt,      // [H]
    const float* __restrict__ C,           // [H, NH]
    const float* __restrict__ log_A_real,  // [H, NH]
    const float* __restrict__ A_imag,      // [H, NH]
    float* __restrict__ out,               // [H, L]
    int L)
{
    __shared__ float4 sm4[TILE / 4];       // 16 KB staging tile

    const int h    = blockIdx.y;
    const int l0   = blockIdx.x * TILE;
    const int t    = threadIdx.x;
    const int lane = t & 31;

    // ---- per-warp setup: lane == n. Mirrors reference fp32 math with
    // MUFU-grade exp/div (rel err ~2^-21 vs the 1e-3 gate).
    float dt     = ex2(log_dt[h] * LOG2E);
    float Ar     = -ex2(log_A_real[h * NH + lane] * LOG2E);
    float Ai     = A_imag[h * NH + lane];
    float dtA    = Ar * dt;
    float den    = Ar * Ar + Ai * Ai;
    float expdtA = ex2(dtA * LOG2E);
    float c      = __fdividef(2.0f * C[h * NH + lane] * (expdtA - 1.0f) * Ar, den);

    const float dtA0  = __shfl_sync(0xffffffffu, dtA, 0);
    const unsigned eq = __ballot_sync(0xffffffffu,
                          __float_as_uint(dtA) == __float_as_uint(dtA0));
    float S = c;
#pragma unroll
    for (int o = 16; o; o >>= 1)
        S += __shfl_xor_sync(0xffffffffu, S, o);

    float* gtile = out + (size_t)h * L + l0;

    if (eq == 0xffffffffu) {
        // ---- hot path: K = S * exp(dtA0 * l), geometric recurrence ----
        const float E   = dtA0 * LOG2E;
        const float q1  = ex2(E);               // adjacent-l ratio
        const float stp = ex2(E * 1024.0f);     // j-step ratio (256 thr * 4)
        float p0 = ex2(E * (float)(l0 + 4 * t));
        float p1 = p0 * q1;
        float p2 = p1 * q1;
        float p3 = p2 * q1;

        ull pa = pack2(p0, p1);
        ull pb = pack2(p2, p3);
        const ull s2  = pack2(S, S);
        const ull st2 = pack2(stp, stp);

        if (l0 + TILE <= L) {
            // full tile: stage in smem, drain via one async bulk copy
#pragma unroll
            for (int j = 0; j < JF; j++) {
                ull va = mul2(pa, s2);
                ull vb = mul2(pb, s2);
                float4 v;
                unpack2(va, v.x, v.y);
                unpack2(vb, v.z, v.w);
                sm4[t + j * TPB] = v;          // STS.128, conflict-free
                pa = mul2(pa, st2);
                pb = mul2(pb, st2);
            }
            __syncthreads();
            if (t == 0) {
                asm volatile("fence.proxy.async.shared::cta;" ::: "memory");
                asm volatile(
                    "cp.async.bulk.global.shared::cta.bulk_group [%0], [%1], %2;"
                    :: "l"(gtile), "r"(smem_u32(sm4)), "r"((int)(TILE * 4))
                    : "memory");
                asm volatile("cp.async.bulk.commit_group;" ::: "memory");
                asm volatile("cp.async.bulk.wait_group 0;" ::: "memory");
            }
        } else {
            // partial tail tile: guarded direct stores
            float4* o = (float4*)gtile + t;
            const int lrem = l0 + 4 * t;
#pragma unroll
            for (int j = 0; j < JF; j++) {
                ull va = mul2(pa, s2);
                ull vb = mul2(pb, s2);
                float4 v;
                unpack2(va, v.x, v.y);
                unpack2(vb, v.z, v.w);
                if (lrem + j * 1024 + 3 < L) o[j * TPB] = v;
                pa = mul2(pa, st2);
                pb = mul2(pb, st2);
            }
        }
    } else {
        // ---- cold path: direct evaluation via shfl-gathered coefficients ----
        const int wbase = l0 + (t >> 5) * (TILE / 8);   // 512 elems per warp
        for (int k = 0; k < (TILE / 8) / 32; k++) {
            const int l = wbase + lane + k * 32;
            float lf = (float)l;
            float acc = 0.0f;
#pragma unroll
            for (int i = 0; i < NH; i++) {
                float ci = __shfl_sync(0xffffffffu, c,   i);
                float di = __shfl_sync(0xffffffffu, dtA, i);
                acc += ci * ex2(di * LOG2E * lf);
            }
            if (l < L) out[(size_t)h * L + l] = acc;
        }
    }
}

extern "C" void kernel_launch(void* const* d_in, const int* in_sizes, int n_in,
                              void* d_out, int out_size)
{
    const float* log_dt     = (const float*)d_in[0];
    const float* C          = (const float*)d_in[1];
    const float* log_A_real = (const float*)d_in[2];
    const float* A_imag     = (const float*)d_in[3];
    float* out = (float*)d_out;

    const int H = in_sizes[0];
    const int L = out_size / H;

    dim3 grid((L + TILE - 1) / TILE, H);
    s4d_kernel<<<grid, TPB>>>(log_dt, C, log_A_real, A_imag, out, L);
}

// round 8
// speedup vs baseline: 1.2454x; 1.2454x over previous
#include <cuda_runtime.h>
#include <cstdint>

// S4D Vandermonde kernel:  K[h,l] = 2 * sum_n C_eff[h,n] * exp(dtA[h,n] * l)
// H=256, NH=N/2=32, L=16384.
//
// With this problem's init dtA[h,n] is constant across n, so
// K[h,l] = S[h] * exp(dtA[h]*l): one geometric recurrence per head.
// Warp-autonomous (R6 structure — the best measured): each warp owns a
// (head, 512-elem chunk); lane=n computes per-head params, ballot checks
// bitwise n-uniformity of dtA, shfl-reduce gives S.
// R8 deltas vs R6: S folded into the recurrence seed (p0 = S*exp(E*lb)), so
// the hot loop is store+2 mul.f32x2 instead of 4; exp(dtA) reused as the
// adjacent-l ratio q1 (one fewer MUFU in the serial chain); raw ex2.approx +
// __fdividef prologue (R7's safe trims). Direct STG.128 stores (the R7
// smem+bulk-copy path regressed and is reverted).

#define TPB    256
#define NH     32
#define WPB    (TPB / 32)      // warps per block
#define JF     4               // float4 stores per lane
#define WCHUNK (32 * 4 * JF)   // 512 l-elements per warp
#define LOG2E  1.4426950408889634f

typedef unsigned long long ull;

__device__ __forceinline__ float ex2(float x) {
    float y; asm("ex2.approx.f32 %0, %1;" : "=f"(y) : "f"(x));
    return y;
}
__device__ __forceinline__ ull mul2(ull a, ull b) {
    ull d; asm("mul.rn.f32x2 %0, %1, %2;" : "=l"(d) : "l"(a), "l"(b));
    return d;
}
__device__ __forceinline__ ull pack2(float lo, float hi) {
    ull u; asm("mov.b64 %0, {%1, %2};" : "=l"(u) : "f"(lo), "f"(hi));
    return u;
}
__device__ __forceinline__ void unpack2(ull u, float& lo, float& hi) {
    asm("mov.b64 {%0, %1}, %2;" : "=f"(lo), "=f"(hi) : "l"(u));
}

__global__ void __launch_bounds__(TPB) s4d_kernel(
    const float* __restrict__ log_dt,      // [H]
    const float* __restrict__ C,           // [H, NH]
    const float* __restrict__ log_A_real,  // [H, NH]
    const float* __restrict__ A_imag,      // [H, NH]
    float* __restrict__ out,               // [H, L]
    int L)
{
    const int h     = blockIdx.y;
    const int lane  = threadIdx.x & 31;
    const int chunk = blockIdx.x * WPB + (threadIdx.x >> 5);
    const int cbase = chunk * WCHUNK;
    if (cbase >= L) return;

    // ---- per-warp setup: lane == n. Mirrors reference fp32 math with
    // MUFU-grade exp/div (rel err ~2^-21 vs the 1e-3 gate).
    float dt     = ex2(log_dt[h] * LOG2E);
    float Ar     = -ex2(log_A_real[h * NH + lane] * LOG2E);
    float Ai     = A_imag[h * NH + lane];
    float dtA    = Ar * dt;
    float den    = Ar * Ar + Ai * Ai;
    float expdtA = ex2(dtA * LOG2E);
    float c      = __fdividef(2.0f * C[h * NH + lane] * (expdtA - 1.0f) * Ar, den);

    const float dtA0  = __shfl_sync(0xffffffffu, dtA, 0);
    const unsigned eq = __ballot_sync(0xffffffffu,
                          __float_as_uint(dtA) == __float_as_uint(dtA0));
    float S = c;
#pragma unroll
    for (int o = 16; o; o >>= 1)
        S += __shfl_xor_sync(0xffffffffu, S, o);

    float* obase = out + (size_t)h * L + cbase;

    if (eq == 0xffffffffu) {
        // ---- hot path: K = S * exp(dtA0 * l), geometric recurrence.
        // S is folded into the seed so the loop is store + 2 mul.f32x2.
        // On this path dtA == dtA0 for every lane, so q1 = expdtA (no extra MUFU).
        const float E   = dtA0 * LOG2E;
        const float q1  = expdtA;                // adjacent-l ratio exp(dtA0)
        const float stp = ex2(E * 128.0f);       // j-step ratio (32 lanes * 4)
        float p0 = S * ex2(E * (float)(cbase + 4 * lane));
        float p1 = p0 * q1;
        float p2 = p1 * q1;
        float p3 = p2 * q1;

        ull pa = pack2(p0, p1);
        ull pb = pack2(p2, p3);
        const ull st2 = pack2(stp, stp);

        float4* o = (float4*)(obase) + lane;
        if (cbase + WCHUNK <= L) {
#pragma unroll
            for (int j = 0; j < JF; j++) {
                float4 v;
                unpack2(pa, v.x, v.y);
                unpack2(pb, v.z, v.w);
                o[j * 32] = v;                   // unconditional STG.128
                pa = mul2(pa, st2);
                pb = mul2(pb, st2);
            }
        } else {
            const int lrem = cbase + 4 * lane;
#pragma unroll
            for (int j = 0; j < JF; j++) {
                float4 v;
                unpack2(pa, v.x, v.y);
                unpack2(pb, v.z, v.w);
                if (lrem + j * 128 + 3 < L) o[j * 32] = v;
                pa = mul2(pa, st2);
                pb = mul2(pb, st2);
            }
        }
    } else {
        // ---- cold path: direct evaluation via shfl-gathered coefficients ----
        for (int k = 0; k < WCHUNK / 32; k++) {
            const int l = cbase + lane + k * 32;
            float lf = (float)l;
            float acc = 0.0f;
#pragma unroll
            for (int i = 0; i < NH; i++) {
                float ci = __shfl_sync(0xffffffffu, c,   i);
                float di = __shfl_sync(0xffffffffu, dtA, i);
                acc += ci * ex2(di * LOG2E * lf);
            }
            if (l < L) obase[lane + k * 32] = acc;
        }
    }
}

extern "C" void kernel_launch(void* const* d_in, const int* in_sizes, int n_in,
                              void* d_out, int out_size)
{
    const float* log_dt     = (const float*)d_in[0];
    const float* C          = (const float*)d_in[1];
    const float* log_A_real = (const float*)d_in[2];
    const float* A_imag     = (const float*)d_in[3];
    float* out = (float*)d_out;

    const int H = in_sizes[0];
    const int L = out_size / H;

    const int chunks = (L + WCHUNK - 1) / WCHUNK;       // warps per head
    dim3 grid((chunks + WPB - 1) / WPB, H);
    s4d_kernel<<<grid, TPB>>>(log_dt, C, log_A_real, A_imag, out, L);
}